// round 1
// baseline (speedup 1.0000x reference)
#include <cuda_runtime.h>
#include <math.h>

#define N_NODES 8192
#define DIM 64
#define KSEL 32

// Scratch (static __device__ arrays — allocation-free per harness rules)
__device__ float g_A[N_NODES * 128];            // [v1_i | -v2_i] row-major
__device__ float g_B[N_NODES * 128];            // [v2_j |  v1_j] row-major
__device__ float g_adj[(size_t)N_NODES * N_NODES];  // 256MB adjacency scratch

// ---------------------------------------------------------------------------
// Kernel 1: v1 = gelu(emb @ W1^T + b1), v2 = gelu(emb @ W2^T + b2)
// Pack g_A[i] = [v1_i, -v2_i], g_B[j] = [v2_j, v1_j] so adj = A @ B^T (K=128).
// ---------------------------------------------------------------------------
__global__ void __launch_bounds__(128) prep_kernel(
    const float* __restrict__ emb,
    const float* __restrict__ W1, const float* __restrict__ b1,
    const float* __restrict__ W2, const float* __restrict__ b2)
{
    __shared__ float sW[2][64][65];   // padded: row-indexed reads conflict-free
    __shared__ float sb[2][64];
    __shared__ float semb[16][64];

    const int tid = threadIdx.x;

    for (int i = tid; i < 64 * 64; i += 128) {
        int r = i >> 6, k = i & 63;
        sW[0][r][k] = W1[i];
        sW[1][r][k] = W2[i];
    }
    if (tid < 64) { sb[0][tid] = b1[tid]; sb[1][tid] = b2[tid]; }

    const int nodeBase = blockIdx.x * 16;
    for (int i = tid; i < 16 * 64; i += 128) {
        semb[i >> 6][i & 63] = emb[(size_t)(nodeBase + (i >> 6)) * 64 + (i & 63)];
    }
    __syncthreads();

    const int h = tid >> 6;      // 0 -> W1/v1, 1 -> W2/v2
    const int r = tid & 63;      // output unit
    for (int n = 0; n < 16; n++) {
        float acc = sb[h][r];
#pragma unroll
        for (int k = 0; k < 64; k++)
            acc = fmaf(semb[n][k], sW[h][r][k], acc);
        // exact (erf) GELU, ALPHA = 1
        float v = 0.5f * acc * (1.0f + erff(acc * 0.70710678118654752f));
        const int node = nodeBase + n;
        if (h == 0) {
            g_A[node * 128 + r]       = v;   // v1
            g_B[node * 128 + 64 + r]  = v;   // v1 in back half of B
        } else {
            g_A[node * 128 + 64 + r]  = -v;  // -v2
            g_B[node * 128 + r]       = v;   // v2 in front half of B
        }
    }
}

// ---------------------------------------------------------------------------
// Kernel 2: adj = relu(A @ B^T), 128x128 CTA tile, 8x8 micro-tile, K=128
// smem staged in K-chunks of 32.
// ---------------------------------------------------------------------------
__global__ void __launch_bounds__(256) gemm_kernel()
{
    __shared__ float As[32][132];   // As[k][i], pad 132 keeps 16B alignment
    __shared__ float Bs[32][132];   // Bs[k][j]

    const int tid = threadIdx.x;
    const int tx = tid & 15;        // col group (8 cols each)
    const int ty = tid >> 4;        // row group (8 rows each)
    const int rowBase = blockIdx.y * 128;
    const int colBase = blockIdx.x * 128;

    float acc[8][8];
#pragma unroll
    for (int i = 0; i < 8; i++)
#pragma unroll
        for (int j = 0; j < 8; j++) acc[i][j] = 0.0f;

    const int li = tid >> 3;          // 0..31: row/col within tile for staging
    const int lk = (tid & 7) * 4;     // 0..28: k offset (float4)

    for (int kb = 0; kb < 128; kb += 32) {
#pragma unroll
        for (int l = 0; l < 4; l++) {
            const int i = li + l * 32;
            float4 va = *(const float4*)&g_A[(size_t)(rowBase + i) * 128 + kb + lk];
            As[lk + 0][i] = va.x; As[lk + 1][i] = va.y;
            As[lk + 2][i] = va.z; As[lk + 3][i] = va.w;
            float4 vb = *(const float4*)&g_B[(size_t)(colBase + i) * 128 + kb + lk];
            Bs[lk + 0][i] = vb.x; Bs[lk + 1][i] = vb.y;
            Bs[lk + 2][i] = vb.z; Bs[lk + 3][i] = vb.w;
        }
        __syncthreads();

#pragma unroll 8
        for (int k = 0; k < 32; k++) {
            float a[8], b[8];
            float4 a0 = *(const float4*)&As[k][ty * 8];
            float4 a1 = *(const float4*)&As[k][ty * 8 + 4];
            float4 b0 = *(const float4*)&Bs[k][tx * 8];
            float4 b1 = *(const float4*)&Bs[k][tx * 8 + 4];
            a[0] = a0.x; a[1] = a0.y; a[2] = a0.z; a[3] = a0.w;
            a[4] = a1.x; a[5] = a1.y; a[6] = a1.z; a[7] = a1.w;
            b[0] = b0.x; b[1] = b0.y; b[2] = b0.z; b[3] = b0.w;
            b[4] = b1.x; b[5] = b1.y; b[6] = b1.z; b[7] = b1.w;
#pragma unroll
            for (int i = 0; i < 8; i++)
#pragma unroll
                for (int j = 0; j < 8; j++)
                    acc[i][j] = fmaf(a[i], b[j], acc[i][j]);
        }
        __syncthreads();
    }

    // epilogue: relu + store
#pragma unroll
    for (int ri = 0; ri < 8; ri++) {
        const size_t rowOff = (size_t)(rowBase + ty * 8 + ri) * N_NODES + colBase + tx * 8;
        float4 o0, o1;
        o0.x = fmaxf(acc[ri][0], 0.0f); o0.y = fmaxf(acc[ri][1], 0.0f);
        o0.z = fmaxf(acc[ri][2], 0.0f); o0.w = fmaxf(acc[ri][3], 0.0f);
        o1.x = fmaxf(acc[ri][4], 0.0f); o1.y = fmaxf(acc[ri][5], 0.0f);
        o1.z = fmaxf(acc[ri][6], 0.0f); o1.w = fmaxf(acc[ri][7], 0.0f);
        *(float4*)&g_adj[rowOff]     = o0;
        *(float4*)&g_adj[rowOff + 4] = o1;
    }
}

// ---------------------------------------------------------------------------
// Kernel 3: per-row top-32 of (adj + 0.01*noise), write out = adj * mask.
// One CTA (256 threads) per row; scores cached in 32 registers per thread;
// 32 rounds of exact block argmax (tie-break: smaller index, matching top_k).
// ---------------------------------------------------------------------------
__global__ void __launch_bounds__(256) topk_kernel(
    const float* __restrict__ noise, float* __restrict__ out)
{
    const int row = blockIdx.x;
    const int tid = threadIdx.x;
    const size_t base = (size_t)row * N_NODES;

    float s[32];
#pragma unroll
    for (int e = 0; e < 32; e++) {
        const int j = tid + (e << 8);
        const float a  = g_adj[base + j];
        const float nz = noise[base + j];
        // match ref rounding: (noise * 0.01) then add — no fma contraction
        s[e] = __fadd_rn(a, __fmul_rn(0.01f, nz));
    }

    unsigned excl = 0u;
    float bv = -1e30f;
    int   bj = 0x7fffffff;
#pragma unroll
    for (int e = 0; e < 32; e++) {          // ascending e => ascending j; strict >
        if (s[e] > bv) { bv = s[e]; bj = tid + (e << 8); }
    }

    __shared__ float wv[8];
    __shared__ int   wj[8];
    __shared__ int   wt[8];
    __shared__ int   selj[KSEL];
    __shared__ int   wint;

    for (int r = 0; r < KSEL; r++) {
        float v = bv; int j = bj; int t = tid;
#pragma unroll
        for (int off = 16; off > 0; off >>= 1) {
            float ov = __shfl_down_sync(0xffffffffu, v, off);
            int   oj = __shfl_down_sync(0xffffffffu, j, off);
            int   ot = __shfl_down_sync(0xffffffffu, t, off);
            if (ov > v || (ov == v && oj < j)) { v = ov; j = oj; t = ot; }
        }
        if ((tid & 31) == 0) { wv[tid >> 5] = v; wj[tid >> 5] = j; wt[tid >> 5] = t; }
        __syncthreads();
        if (tid == 0) {
            float Bv = wv[0]; int Bj = wj[0]; int Bt = wt[0];
#pragma unroll
            for (int w = 1; w < 8; w++) {
                if (wv[w] > Bv || (wv[w] == Bv && wj[w] < Bj)) {
                    Bv = wv[w]; Bj = wj[w]; Bt = wt[w];
                }
            }
            selj[r] = Bj;
            wint = Bt;
        }
        __syncthreads();
        if (tid == wint) {
            const int e = (selj[r] - tid) >> 8;
            excl |= (1u << e);
            // rescan remaining
            bv = -1e30f; bj = 0x7fffffff;
#pragma unroll
            for (int e2 = 0; e2 < 32; e2++) {
                if (!((excl >> e2) & 1u)) {
                    if (s[e2] > bv) { bv = s[e2]; bj = tid + (e2 << 8); }
                }
            }
        }
        // winner's new (bv,bj) is private-register state; next round's shuffle
        // reduction reads it in program order — no extra sync needed.
    }
    __syncthreads();

    // zero the output row, then scatter the 32 selected adj values
    const float4 z4 = make_float4(0.0f, 0.0f, 0.0f, 0.0f);
#pragma unroll
    for (int q = 0; q < 8; q++) {
        ((float4*)(out + base))[tid + (q << 8)] = z4;
    }
    __syncthreads();
    if (tid < KSEL) {
        const int j = selj[tid];
        out[base + j] = g_adj[base + j];
    }
}

// ---------------------------------------------------------------------------
extern "C" void kernel_launch(void* const* d_in, const int* in_sizes, int n_in,
                              void* d_out, int out_size)
{
    const float* emb   = (const float*)d_in[0];
    const float* noise = (const float*)d_in[1];
    const float* W1    = (const float*)d_in[2];
    const float* b1    = (const float*)d_in[3];
    const float* W2    = (const float*)d_in[4];
    const float* b2    = (const float*)d_in[5];
    float* out = (float*)d_out;

    prep_kernel<<<N_NODES / 16, 128>>>(emb, W1, b1, W2, b2);

    dim3 g(N_NODES / 128, N_NODES / 128);
    gemm_kernel<<<g, 256>>>();

    topk_kernel<<<N_NODES, 256>>>(noise, out);
}

// round 3
// speedup vs baseline: 1.4591x; 1.4591x over previous
#include <cuda_runtime.h>
#include <cuda_bf16.h>
#include <math.h>
#include <stdint.h>

#define N_NODES 8192
#define KSEL 32

// ---------------------------------------------------------------------------
// Scratch (__device__ globals; allocation-free per harness rules)
// ---------------------------------------------------------------------------
__device__ float g_Af[N_NODES * 128];                 // [v1 | -v2] fp32 (exact rescore)
__device__ float g_Bf[N_NODES * 128];                 // [v2 |  v1] fp32
__device__ __nv_bfloat16 g_Abf[N_NODES * 384];        // [Ahi | Alo | Ahi]
__device__ __nv_bfloat16 g_Bbf[N_NODES * 384];        // [Bhi | Bhi | Blo]
__device__ float g_score[(size_t)N_NODES * N_NODES];  // approx relu(adj)+0.01*noise

__device__ __forceinline__ uint32_t smem_u32(const void* p) {
    uint32_t a;
    asm("{ .reg .u64 t; cvta.to.shared.u64 t, %1; cvt.u32.u64 %0, t; }" : "=r"(a) : "l"(p));
    return a;
}
__device__ __forceinline__ uint32_t sw128(uint32_t byte) {   // Swizzle<3,4,3>
    return byte ^ ((byte >> 3) & 0x70);
}
__device__ __forceinline__ void ldmatrix_x4(uint32_t& r0, uint32_t& r1,
                                            uint32_t& r2, uint32_t& r3, uint32_t addr) {
    asm volatile("ldmatrix.sync.aligned.m8n8.x4.shared.b16 {%0,%1,%2,%3}, [%4];"
                 : "=r"(r0), "=r"(r1), "=r"(r2), "=r"(r3) : "r"(addr));
}
__device__ __forceinline__ void mma_bf16(float* c, const uint32_t* a, uint32_t b0, uint32_t b1) {
    asm volatile("mma.sync.aligned.m16n8k16.row.col.f32.bf16.bf16.f32 "
                 "{%0,%1,%2,%3}, {%4,%5,%6,%7}, {%8,%9}, {%0,%1,%2,%3};"
                 : "+f"(c[0]), "+f"(c[1]), "+f"(c[2]), "+f"(c[3])
                 : "r"(a[0]), "r"(a[1]), "r"(a[2]), "r"(a[3]), "r"(b0), "r"(b1));
}

// ---------------------------------------------------------------------------
// Kernel 1: v1/v2 prep + fp32 pack + bf16 hi/lo split pack
// ---------------------------------------------------------------------------
__global__ void __launch_bounds__(128) prep_kernel(
    const float* __restrict__ emb,
    const float* __restrict__ W1, const float* __restrict__ b1,
    const float* __restrict__ W2, const float* __restrict__ b2)
{
    __shared__ float sW[2][64][65];
    __shared__ float sb[2][64];
    __shared__ float semb[16][64];

    const int tid = threadIdx.x;
    for (int i = tid; i < 64 * 64; i += 128) {
        int r = i >> 6, k = i & 63;
        sW[0][r][k] = W1[i];
        sW[1][r][k] = W2[i];
    }
    if (tid < 64) { sb[0][tid] = b1[tid]; sb[1][tid] = b2[tid]; }

    const int nodeBase = blockIdx.x * 16;
    for (int i = tid; i < 16 * 64; i += 128)
        semb[i >> 6][i & 63] = emb[(size_t)(nodeBase + (i >> 6)) * 64 + (i & 63)];
    __syncthreads();

    const int h = tid >> 6;
    const int r = tid & 63;
    for (int n = 0; n < 16; n++) {
        float acc = sb[h][r];
#pragma unroll
        for (int k = 0; k < 64; k++)
            acc = fmaf(semb[n][k], sW[h][r][k], acc);
        float v = 0.5f * acc * (1.0f + erff(acc * 0.70710678118654752f));
        const int node = nodeBase + n;

        if (h == 0) {
            g_Af[node * 128 + r]      = v;      // v1 in A front half
            g_Bf[node * 128 + 64 + r] = v;      // v1 in B back half
            __nv_bfloat16 hi = __float2bfloat16_rn(v);
            __nv_bfloat16 lo = __float2bfloat16_rn(v - __bfloat162float(hi));
            g_Abf[node * 384 + r]        = hi;
            g_Abf[node * 384 + 128 + r]  = lo;
            g_Abf[node * 384 + 256 + r]  = hi;
            g_Bbf[node * 384 + 64 + r]       = hi;
            g_Bbf[node * 384 + 128 + 64 + r] = hi;
            g_Bbf[node * 384 + 256 + 64 + r] = lo;
        } else {
            float av = -v;
            g_Af[node * 128 + 64 + r] = av;     // -v2 in A back half
            g_Bf[node * 128 + r]      = v;      //  v2 in B front half
            __nv_bfloat16 ahi = __float2bfloat16_rn(av);
            __nv_bfloat16 alo = __float2bfloat16_rn(av - __bfloat162float(ahi));
            g_Abf[node * 384 + 64 + r]       = ahi;
            g_Abf[node * 384 + 128 + 64 + r] = alo;
            g_Abf[node * 384 + 256 + 64 + r] = ahi;
            __nv_bfloat16 bhi = __float2bfloat16_rn(v);
            __nv_bfloat16 blo = __float2bfloat16_rn(v - __bfloat162float(bhi));
            g_Bbf[node * 384 + r]       = bhi;
            g_Bbf[node * 384 + 128 + r] = bhi;
            g_Bbf[node * 384 + 256 + r] = blo;
        }
    }
}

// ---------------------------------------------------------------------------
// Kernel 2: mma.sync bf16 split GEMM: g_score = relu(A'B'^T) + 0.01*noise
// CTA 128x128, K=384 in 6 chunks of 64. 8 warps (4m x 2n), warp tile 32x64.
// ---------------------------------------------------------------------------
#define CHUNK_BYTES 16384              // 128 rows x 64 bf16 (128B/row)
#define SMEM_TOT (4 * CHUNK_BYTES)     // A0 A1 B0 B1 = 64KB

__global__ void __launch_bounds__(256) gemm_kernel(const float* __restrict__ noise)
{
    extern __shared__ char smem[];
    const uint32_t sbase = smem_u32(smem);
    const int tid = threadIdx.x;
    const int lane = tid & 31;
    const int warp = tid >> 5;
    const int warpM = warp & 3;         // 0..3 -> 32-row slices
    const int warpN = warp >> 2;        // 0..1 -> 64-col slices
    const int rowBase = blockIdx.y * 128;
    const int colBase = blockIdx.x * 128;

    // smem offsets: A buf0, A buf1, B buf0, B buf1
    const uint32_t offA[2] = {0u, CHUNK_BYTES};
    const uint32_t offB[2] = {2 * CHUNK_BYTES, 3 * CHUNK_BYTES};

    const int ldRow = tid >> 3;         // 0..31 (x4 groups of 32 rows)
    const int ldQ = tid & 7;            // 16B segment within 128B row

    // per-thread swizzled smem store offsets (4 row-groups per tile)
    uint32_t stOff[4];
#pragma unroll
    for (int g = 0; g < 4; g++)
        stOff[g] = sw128((ldRow + g * 32) * 128 + ldQ * 16);

    // global load helper: chunk c -> regs
    const char* gA = (const char*)g_Abf;
    const char* gB = (const char*)g_Bbf;

    uint4 ra[4], rb[4];
    {
        const int c = 0;
#pragma unroll
        for (int g = 0; g < 4; g++) {
            ra[g] = *(const uint4*)(gA + (size_t)(rowBase + ldRow + g * 32) * 768 + c * 128 + ldQ * 16);
            rb[g] = *(const uint4*)(gB + (size_t)(colBase + ldRow + g * 32) * 768 + c * 128 + ldQ * 16);
        }
#pragma unroll
        for (int g = 0; g < 4; g++) {
            *(uint4*)(smem + offA[0] + stOff[g]) = ra[g];
            *(uint4*)(smem + offB[0] + stOff[g]) = rb[g];
        }
    }
    __syncthreads();

    float acc[2][8][4];
#pragma unroll
    for (int mi = 0; mi < 2; mi++)
#pragma unroll
        for (int ng = 0; ng < 8; ng++)
#pragma unroll
            for (int q = 0; q < 4; q++) acc[mi][ng][q] = 0.0f;

    const int laneRow = lane & 15;
    const int laneK = lane >> 4;

    for (int c = 0; c < 6; c++) {
        const int buf = c & 1;

        // prefetch next chunk into regs (overlaps with mma)
        if (c < 5) {
#pragma unroll
            for (int g = 0; g < 4; g++) {
                ra[g] = *(const uint4*)(gA + (size_t)(rowBase + ldRow + g * 32) * 768 + (c + 1) * 128 + ldQ * 16);
                rb[g] = *(const uint4*)(gB + (size_t)(colBase + ldRow + g * 32) * 768 + (c + 1) * 128 + ldQ * 16);
            }
        }

        // compute: 4 k16-steps on this 64-wide chunk
#pragma unroll
        for (int ks = 0; ks < 4; ks++) {
            uint32_t afr[2][4];
#pragma unroll
            for (int mi = 0; mi < 2; mi++) {
                uint32_t byte = (warpM * 32 + mi * 16 + laneRow) * 128 + ks * 32 + laneK * 16;
                ldmatrix_x4(afr[mi][0], afr[mi][1], afr[mi][2], afr[mi][3],
                            sbase + offA[buf] + sw128(byte));
            }
#pragma unroll
            for (int nq = 0; nq < 4; nq++) {
                uint32_t r0, r1, r2, r3;
                uint32_t byte = (warpN * 64 + nq * 16 + laneRow) * 128 + ks * 32 + laneK * 16;
                ldmatrix_x4(r0, r1, r2, r3, sbase + offB[buf] + sw128(byte));
#pragma unroll
                for (int mi = 0; mi < 2; mi++) {
                    mma_bf16(acc[mi][nq * 2],     afr[mi], r0, r2);
                    mma_bf16(acc[mi][nq * 2 + 1], afr[mi], r1, r3);
                }
            }
        }

        if (c < 5) {
            __syncthreads();   // everyone done reading buf^1 from previous round
#pragma unroll
            for (int g = 0; g < 4; g++) {
                *(uint4*)(smem + offA[buf ^ 1] + stOff[g]) = ra[g];
                *(uint4*)(smem + offB[buf ^ 1] + stOff[g]) = rb[g];
            }
            __syncthreads();
        }
    }

    // Epilogue: relu + 0.01*noise, direct stores (float2 per fragment pair)
#pragma unroll
    for (int mi = 0; mi < 2; mi++) {
        const int r0 = rowBase + warpM * 32 + mi * 16 + (lane >> 2);
#pragma unroll
        for (int ng = 0; ng < 8; ng++) {
            const int col = colBase + warpN * 64 + ng * 8 + (lane & 3) * 2;
            {
                const size_t g0 = (size_t)r0 * N_NODES + col;
                float2 nz = *(const float2*)(noise + g0);
                float2 o;
                o.x = fmaxf(acc[mi][ng][0], 0.0f) + 0.01f * nz.x;
                o.y = fmaxf(acc[mi][ng][1], 0.0f) + 0.01f * nz.y;
                *(float2*)(g_score + g0) = o;
            }
            {
                const size_t g1 = (size_t)(r0 + 8) * N_NODES + col;
                float2 nz = *(const float2*)(noise + g1);
                float2 o;
                o.x = fmaxf(acc[mi][ng][2], 0.0f) + 0.01f * nz.x;
                o.y = fmaxf(acc[mi][ng][3], 0.0f) + 0.01f * nz.y;
                *(float2*)(g_score + g1) = o;
            }
        }
    }
}

// ---------------------------------------------------------------------------
// Kernel 3: threshold-filter top-K with exact fp32 rescore
// ---------------------------------------------------------------------------
__global__ void __launch_bounds__(256) topk_kernel(
    const float* __restrict__ noise, float* __restrict__ out)
{
    const int row = blockIdx.x;
    const int tid = threadIdx.x;
    const int wid = tid >> 5, lane = tid & 31;
    const size_t base = (size_t)row * N_NODES;

    unsigned ub[32];
#pragma unroll
    for (int e = 0; e < 32; e++)
        ub[e] = __float_as_uint(g_score[base + tid + (e << 8)]);  // scores >= 0

    __shared__ int wsum[8];
    __shared__ int sCnt;
    __shared__ alignas(16) float af[128];
    __shared__ int cand[512];
    __shared__ int nc;
    __shared__ unsigned long long keys[512];
    __shared__ float av[512];
    __shared__ int selj[KSEL];
    __shared__ float selv[KSEL];

    if (tid < 128) af[tid] = g_Af[(size_t)row * 128 + tid];
    if (tid == 0) nc = 0;

    // integer binary search on float bits: count(score > T) in [96, 384]
    unsigned lo = 0, hi = 0x7F800000u, T = 0;
    for (int it = 0; it < 32; it++) {
        unsigned mid = lo + ((hi - lo) >> 1);
        int c = 0;
#pragma unroll
        for (int e = 0; e < 32; e++) c += (ub[e] > mid);
#pragma unroll
        for (int off = 16; off > 0; off >>= 1)
            c += __shfl_down_sync(0xffffffffu, c, off);
        if (lane == 0) wsum[wid] = c;
        __syncthreads();
        if (tid == 0) {
            int t = 0;
#pragma unroll
            for (int w = 0; w < 8; w++) t += wsum[w];
            sCnt = t;
        }
        __syncthreads();
        int cnt = sCnt;
        T = mid;
        if (cnt > 384)      lo = mid + 1;
        else if (cnt < 96)  hi = mid;
        else break;
        if (lo >= hi) break;
        __syncthreads();
    }

    // gather candidates
#pragma unroll
    for (int e = 0; e < 32; e++) {
        if (ub[e] > T) {
            int p = atomicAdd(&nc, 1);
            if (p < 512) cand[p] = tid + (e << 8);
        }
    }
    __syncthreads();
    const int M = (nc < 512) ? nc : 512;

    // exact fp32 rescore: one candidate per warp (dot over K=128)
    for (int i = wid; i < M; i += 8) {
        const int j = cand[i];
        const float4 b = *(const float4*)(g_Bf + (size_t)j * 128 + lane * 4);
        const float4 a = *(const float4*)(af + lane * 4);
        float p = fmaf(a.x, b.x, fmaf(a.y, b.y, fmaf(a.z, b.z, a.w * b.w)));
#pragma unroll
        for (int off = 16; off > 0; off >>= 1)
            p += __shfl_down_sync(0xffffffffu, p, off);
        if (lane == 0) {
            float adjv = fmaxf(p, 0.0f);
            float sc = __fadd_rn(adjv, __fmul_rn(0.01f, __ldg(noise + base + j)));
            keys[i] = ((unsigned long long)__float_as_uint(sc) << 32)
                    | (unsigned)(0xFFFFFFFFu - (unsigned)j);
            av[i] = adjv;
        }
    }
    __syncthreads();

    // exact top-32 (value desc, index asc) among candidates — warp 0
    if (wid == 0) {
        for (int r = 0; r < KSEL; r++) {
            unsigned long long bk = 0; int bi = -1;
            for (int i = lane; i < M; i += 32)
                if (keys[i] > bk) { bk = keys[i]; bi = i; }
#pragma unroll
            for (int off = 16; off > 0; off >>= 1) {
                unsigned long long ok = __shfl_down_sync(0xffffffffu, bk, off);
                int oi = __shfl_down_sync(0xffffffffu, bi, off);
                if (ok > bk) { bk = ok; bi = oi; }
            }
            if (lane == 0) {
                if (bi >= 0 && bk != 0ull) {
                    selj[r] = cand[bi];
                    selv[r] = av[bi];
                    keys[bi] = 0ull;
                } else selj[r] = -1;
            }
            __syncwarp();
        }
    }
    __syncthreads();

    // zero row, scatter exact selected adj values
    const float4 z4 = make_float4(0.0f, 0.0f, 0.0f, 0.0f);
#pragma unroll
    for (int q = 0; q < 8; q++)
        ((float4*)(out + base))[tid + (q << 8)] = z4;
    __syncthreads();
    if (tid < KSEL) {
        int j = selj[tid];
        if (j >= 0) out[base + j] = selv[tid];
    }
}

// ---------------------------------------------------------------------------
extern "C" void kernel_launch(void* const* d_in, const int* in_sizes, int n_in,
                              void* d_out, int out_size)
{
    const float* emb   = (const float*)d_in[0];
    const float* noise = (const float*)d_in[1];
    const float* W1    = (const float*)d_in[2];
    const float* b1    = (const float*)d_in[3];
    const float* W2    = (const float*)d_in[4];
    const float* b2    = (const float*)d_in[5];
    float* out = (float*)d_out;

    cudaFuncSetAttribute(gemm_kernel, cudaFuncAttributeMaxDynamicSharedMemorySize, SMEM_TOT);

    prep_kernel<<<N_NODES / 16, 128>>>(emb, W1, b1, W2, b2);

    dim3 g(N_NODES / 128, N_NODES / 128);
    gemm_kernel<<<g, 256, SMEM_TOT>>>(noise);

    topk_kernel<<<N_NODES, 256>>>(noise, out);
}